// round 2
// baseline (speedup 1.0000x reference)
#include <cuda_runtime.h>
#include <cuda_bf16.h>
#include <cstdint>

typedef unsigned long long u64;

#define M_SLOTS 60
#define CHANS   256
#define HW      3136           // 56*56
#define NTOT    802816         // 256*3136 elements per memory slot
#define BATCH   64
#define EPS     1e-8f

// Scratch (device globals — no allocation allowed)
__device__ float g_mem_avg[M_SLOTS * CHANS];     // [m][c]
__device__ float g_wT[M_SLOTS * BATCH];          // [m][b]  (transposed weights)

// ---------------- packed f32x2 helpers ----------------
__device__ __forceinline__ u64 fma2(u64 a, u64 b, u64 c) {
    u64 d;
    asm("fma.rn.f32x2 %0, %1, %2, %3;" : "=l"(d) : "l"(a), "l"(b), "l"(c));
    return d;
}
__device__ __forceinline__ u64 pack2(float lo, float hi) {
    u64 d;
    unsigned int l = __float_as_uint(lo), h = __float_as_uint(hi);
    asm("mov.b64 %0, {%1, %2};" : "=l"(d) : "r"(l), "r"(h));
    return d;
}
// 128-bit load as two u64 (no unpack movs)
__device__ __forceinline__ void ldg128_nc(const float* p, u64& a, u64& b) {
    asm("ld.global.nc.v2.b64 {%0, %1}, [%2];" : "=l"(a), "=l"(b) : "l"(p));
}
// 128-bit streaming store from two u64 (no pack movs, L2-evict-first)
__device__ __forceinline__ void stg128_cs(float* p, u64 a, u64 b) {
    asm volatile("st.global.cs.v2.b64 [%0], {%1, %2};" :: "l"(p), "l"(a), "l"(b) : "memory");
}

// ---------------- kernel 1: mean over H,W ----------------
// Warp-per-row: 8 rows per 256-thread block, shfl-only reduction, no syncthreads.
__global__ __launch_bounds__(256) void mean_kernel(const float* __restrict__ mem) {
    const int wrp  = threadIdx.x >> 5;
    const int lane = threadIdx.x & 31;
    const int r = blockIdx.x * 8 + wrp;          // 0 .. 15359
    const float4* p = (const float4*)(mem + (size_t)r * HW);   // 784 float4 per row
    float s = 0.0f;
#pragma unroll 8
    for (int i = lane; i < 784; i += 32) {
        float4 v = __ldcs(p + i);
        s += (v.x + v.y) + (v.z + v.w);
    }
#pragma unroll
    for (int o = 16; o > 0; o >>= 1) s += __shfl_xor_sync(0xffffffffu, s, o);
    if (lane == 0) g_mem_avg[r] = s * (1.0f / (float)HW);
}

// ---------------- kernel 2: cosine sim + softmax -> weights ----------------
// One block per batch b, 256 threads (8 warps).
__global__ void weights_kernel(const float* __restrict__ q) {
    const int b = blockIdx.x;
    const int tid = threadIdx.x;
    const int lane = tid & 31;
    const int wrp = tid >> 5;

    __shared__ float s_cos[M_SLOTS];
    __shared__ float s_qn;

    if (wrp == 0) {
        float s = 0.0f;
        const float* qr = q + b * CHANS;
        for (int i = lane; i < CHANS; i += 32) { float v = qr[i]; s += v * v; }
        for (int o = 16; o > 0; o >>= 1) s += __shfl_xor_sync(0xffffffffu, s, o);
        if (lane == 0) s_qn = sqrtf(s);
    }
    __syncthreads();
    const float qn = fmaxf(s_qn, EPS);

    for (int m = wrp; m < M_SLOTS; m += 8) {
        const float* mr = g_mem_avg + m * CHANS;
        const float* qr = q + b * CHANS;
        float dot = 0.0f, mn2 = 0.0f;
        for (int i = lane; i < CHANS; i += 32) {
            float mv = mr[i];
            dot = fmaf(mv, qr[i], dot);
            mn2 = fmaf(mv, mv, mn2);
        }
        for (int o = 16; o > 0; o >>= 1) {
            dot += __shfl_xor_sync(0xffffffffu, dot, o);
            mn2 += __shfl_xor_sync(0xffffffffu, mn2, o);
        }
        if (lane == 0) s_cos[m] = dot / (qn * fmaxf(sqrtf(mn2), EPS));
    }
    __syncthreads();

    if (wrp == 0) {
        float v0 = (lane < M_SLOTS) ? s_cos[lane] : -1e30f;
        float v1 = (lane + 32 < M_SLOTS) ? s_cos[lane + 32] : -1e30f;
        float mx = fmaxf(v0, v1);
        for (int o = 16; o > 0; o >>= 1) mx = fmaxf(mx, __shfl_xor_sync(0xffffffffu, mx, o));
        float e0 = (lane < M_SLOTS) ? expf(v0 - mx) : 0.0f;
        float e1 = (lane + 32 < M_SLOTS) ? expf(v1 - mx) : 0.0f;
        float sm = e0 + e1;
        for (int o = 16; o > 0; o >>= 1) sm += __shfl_xor_sync(0xffffffffu, sm, o);
        float inv = 1.0f / sm;
        if (lane < M_SLOTS)       g_wT[lane * BATCH + b]        = e0 * inv;
        if (lane + 32 < M_SLOTS)  g_wT[(lane + 32) * BATCH + b] = e1 * inv;
    }
}

// ---------------- kernel 3: einsum bm,mchw->bchw ----------------
// f32x2 lanes = SPATIAL pairs: LDG.128 -> two u64 operands with zero movs.
// Weights pre-packed (w,w) in smem; per-m: 1 LDG.128 + 16 broadcast LDS.64 + 32 FFMA2.
// Thread: 4 spatial (2 pairs) x 16 batches. Grid (4 btiles fastest, 784 chunks)
// keeps the 4 btiles of one chunk co-resident -> memory_pool DRAM-read ~once.
__global__ __launch_bounds__(256, 2) void einsum_kernel(const float* __restrict__ mem,
                                                        float* __restrict__ out) {
    __shared__ u64 s_w2[M_SLOTS][16];   // (w[b], w[b]) duplicated pairs, this btile
    const int btile = blockIdx.x;       // 0..3 -> batches [btile*16, btile*16+16)
    const int tid = threadIdx.x;

    for (int i = tid; i < M_SLOTS * 16; i += 256) {
        int m = i >> 4, b = i & 15;
        float w = g_wT[m * BATCH + btile * 16 + b];
        s_w2[m][b] = pack2(w, w);
    }
    __syncthreads();

    const size_t n0 = (size_t)blockIdx.y * 1024 + (size_t)tid * 4;
    const float* mp = mem + n0;

    u64 acc[16][2];
#pragma unroll
    for (int b = 0; b < 16; b++) { acc[b][0] = 0ull; acc[b][1] = 0ull; }

#pragma unroll 4
    for (int m = 0; m < M_SLOTS; m++) {
        u64 d01, d23;
        ldg128_nc(mp + (size_t)m * NTOT, d01, d23);
#pragma unroll
        for (int b = 0; b < 16; b++) {
            u64 w2 = s_w2[m][b];
            acc[b][0] = fma2(d01, w2, acc[b][0]);
            acc[b][1] = fma2(d23, w2, acc[b][1]);
        }
    }

    float* op = out + n0 + (size_t)(btile * 16) * NTOT;
#pragma unroll
    for (int b = 0; b < 16; b++) {
        stg128_cs(op + (size_t)b * NTOT, acc[b][0], acc[b][1]);
    }
}

// ---------------- launcher ----------------
extern "C" void kernel_launch(void* const* d_in, const int* in_sizes, int n_in,
                              void* d_out, int out_size) {
    const float* mem = (const float*)d_in[0];
    const float* q   = (const float*)d_in[1];
    if (n_in >= 2 && in_sizes[0] < in_sizes[1]) {
        const float* t = mem; mem = q; q = t;
    }
    float* out = (float*)d_out;

    mean_kernel<<<M_SLOTS * CHANS / 8, 256>>>(mem);
    weights_kernel<<<BATCH, 256>>>(q);
    einsum_kernel<<<dim3(4, NTOT / 1024), 256>>>(mem, out);
}